// round 2
// baseline (speedup 1.0000x reference)
#include <cuda_runtime.h>

// Problem constants
#define B_  4
#define C_  16
#define H_  64
#define W_  64
#define F_  32
#define KK  3
#define CC  8            // channels per smem chunk (2 chunks)
#define TW  32           // tile width
#define TH  32           // tile height
#define PITCH 34         // tile row pitch (TW + 2 halo)
#define NTHREADS 256

__device__ __forceinline__ float frcp(float q) {
    float r;
    asm("rcp.approx.f32 %0, %1;" : "=f"(r) : "f"(q));
    return r;
}

__global__ __launch_bounds__(NTHREADS, 3)
void kaconv_kernel(const float* __restrict__ x,
                   const float* __restrict__ nums,
                   const float* __restrict__ denoms,
                   float* __restrict__ out)
{
    // smem: coeffs [C][9][12] floats (padded to 3x float4), then x tile [CC][34][34]
    __shared__ float scf[C_ * 9 * 12];          // 1728 floats = 6912 B
    __shared__ float sx[CC * PITCH * PITCH];    // 9248 floats = 36992 B

    const int tx  = threadIdx.x;        // 0..31
    const int ty  = threadIdx.y;        // 0..7
    const int tid = ty * 32 + tx;
    const int f   = blockIdx.z & (F_ - 1);
    const int b   = blockIdx.z >> 5;
    const int gx0 = blockIdx.x * TW;
    const int gy0 = blockIdx.y * TH;

    // ---- load Pade coefficients for this output filter f ----
    // layout per (c,k): [a0 a1 a2 a3 | a4 a5 b1 b2 | b3 b4 pad pad]
    for (int i = tid; i < C_ * 9; i += NTHREADS) {
        const int c = i / 9;
        const int k = i - c * 9;
        const float* np = nums   + (((f * C_ + c) * 9 + k) * 6);
        const float* dp = denoms + (((f * C_ + c) * 9 + k) * 4);
        float* dst = scf + i * 12;
        #pragma unroll
        for (int n = 0; n < 6; ++n) dst[n] = np[n];
        #pragma unroll
        for (int m = 0; m < 4; ++m) dst[6 + m] = dp[m];
        dst[10] = 0.f; dst[11] = 0.f;
    }

    float acc[4] = {0.f, 0.f, 0.f, 0.f};

    // ---- two channel chunks of 8 ----
    for (int chunk = 0; chunk < 2; ++chunk) {
        const int ch0 = chunk * CC;

        __syncthreads();   // protect prior-iter tile reads / coeff writes

        // stage x tile (8 channels, 34x34 with zero-padded halo)
        const float* xb = x + ((size_t)(b * C_ + ch0)) * (H_ * W_);
        for (int i = tid; i < CC * PITCH * PITCH; i += NTHREADS) {
            const int c  = i / (PITCH * PITCH);
            const int r  = i - c * (PITCH * PITCH);
            const int yy = r / PITCH;
            const int xx = r - yy * PITCH;
            const int gy = gy0 + yy - 1;
            const int gx = gx0 + xx - 1;
            float v = 0.f;
            if ((unsigned)gy < H_ && (unsigned)gx < W_)
                v = xb[c * (H_ * W_) + gy * W_ + gx];
            sx[i] = v;
        }

        __syncthreads();

        // ---- rational conv accumulate ----
        #pragma unroll 1
        for (int c = 0; c < CC; ++c) {
            const float* xc = sx + c * (PITCH * PITCH);
            const float4* cf = (const float4*)(scf + (ch0 + c) * 9 * 12);
            #pragma unroll
            for (int k = 0; k < 9; ++k) {
                const int a  = k / 3;
                const int bb = k - 3 * (k / 3);
                const float4 c0 = cf[k * 3 + 0];   // a0 a1 a2 a3
                const float4 c1 = cf[k * 3 + 1];   // a4 a5 b1 b2
                const float4 c2 = cf[k * 3 + 2];   // b3 b4 -- --
                #pragma unroll
                for (int p = 0; p < 4; ++p) {
                    const float xv = xc[(ty + p * 8 + a) * PITCH + tx + bb];
                    // P(x) = a0 + a1 x + ... + a5 x^5  (Horner)
                    float P = fmaf(c1.y, xv, c1.x);
                    P = fmaf(P, xv, c0.w);
                    P = fmaf(P, xv, c0.z);
                    P = fmaf(P, xv, c0.y);
                    P = fmaf(P, xv, c0.x);
                    // S = b1 + b2 x + b3 x^2 + b4 x^3 ; Q = 1 + |x*S|
                    float S = fmaf(c2.y, xv, c2.x);
                    S = fmaf(S, xv, c1.w);
                    S = fmaf(S, xv, c1.z);
                    const float Q = 1.0f + fabsf(S * xv);
                    acc[p] = fmaf(P, frcp(Q), acc[p]);
                }
            }
        }
    }

    // ---- write (B,F,H,W): 4 rows per thread, fully coalesced ----
    float* op = out + ((size_t)blockIdx.z * H_ + gy0 + ty) * W_ + gx0 + tx;
    #pragma unroll
    for (int p = 0; p < 4; ++p)
        op[(size_t)(p * 8) * W_] = acc[p];
}

extern "C" void kernel_launch(void* const* d_in, const int* in_sizes, int n_in,
                              void* d_out, int out_size) {
    const float* x      = (const float*)d_in[0];
    const float* nums   = (const float*)d_in[1];
    const float* denoms = (const float*)d_in[2];
    float* out = (float*)d_out;

    dim3 grid(W_ / TW, H_ / TH, B_ * F_);   // 2 x 2 x 128
    dim3 block(32, 8);
    kaconv_kernel<<<grid, block>>>(x, nums, denoms, out);
}

// round 3
// speedup vs baseline: 1.0654x; 1.0654x over previous
#include <cuda_runtime.h>

// Problem constants
#define B_  4
#define C_  16
#define H_  64
#define W_  64
#define F_  32
#define CC  8            // channels per smem chunk (2 chunks)
#define TW  32           // tile width
#define TH  32           // tile height
#define PITCH 34         // tile row pitch (TW + 2 halo)
#define NTHREADS 256

typedef unsigned long long ull;

__device__ __forceinline__ float frcp(float q) {
    float r;
    asm("rcp.approx.f32 %0, %1;" : "=f"(r) : "f"(q));
    return r;
}
// pack two f32 into one .b64 (one MOV.64)
__device__ __forceinline__ ull pack2(float lo, float hi) {
    ull r;
    asm("mov.b64 %0, {%1, %2};" : "=l"(r) : "f"(lo), "f"(hi));
    return r;
}
__device__ __forceinline__ void unpack2(ull v, float& lo, float& hi) {
    asm("mov.b64 {%0, %1}, %2;" : "=f"(lo), "=f"(hi) : "l"(v));
}
// Blackwell packed f32x2 FMA / MUL (ptxas never auto-emits these)
__device__ __forceinline__ ull fma2(ull a, ull b, ull c) {
    ull d;
    asm("fma.rn.f32x2 %0, %1, %2, %3;" : "=l"(d) : "l"(a), "l"(b), "l"(c));
    return d;
}
__device__ __forceinline__ ull mul2(ull a, ull b) {
    ull d;
    asm("mul.rn.f32x2 %0, %1, %2;" : "=l"(d) : "l"(a), "l"(b));
    return d;
}

__global__ __launch_bounds__(NTHREADS, 4)
void kaconv_kernel(const float* __restrict__ x,
                   const float* __restrict__ nums,
                   const float* __restrict__ denoms,
                   float* __restrict__ out)
{
    // Coeffs stored DUPLICATED: each scalar coeff occupies one double slot with
    // both f32 lanes equal -> double2 LDS.128 yields two broadcast-packed f32x2
    // coefficients in register pairs with no pack instructions.
    __shared__ __align__(16) double scf[C_ * 9 * 10];   // 11520 B
    __shared__ float sx[CC * PITCH * PITCH];            // 36992 B  (total 48512 <= 48K static)

    const int tx  = threadIdx.x;        // 0..31
    const int ty  = threadIdx.y;        // 0..7
    const int tid = ty * 32 + tx;
    const int f   = blockIdx.z & (F_ - 1);
    const int b   = blockIdx.z >> 5;
    const int gx0 = blockIdx.x * TW;
    const int gy0 = blockIdx.y * TH;

    // ---- stage Pade coefficients for filter f, duplicated into f32x2 slots ----
    // slot order per (c,k): a0 a1 a2 a3 a4 a5 b1 b2 b3 b4
    for (int i = tid; i < C_ * 9; i += NTHREADS) {
        const float* np = nums   + (size_t)f * (C_ * 9 * 6) + i * 6;
        const float* dp = denoms + (size_t)f * (C_ * 9 * 4) + i * 4;
        double* dst = scf + i * 10;
        #pragma unroll
        for (int n = 0; n < 6; ++n) {
            float v = np[n];
            dst[n] = __longlong_as_double((long long)pack2(v, v));
        }
        #pragma unroll
        for (int m = 0; m < 4; ++m) {
            float v = dp[m];
            dst[6 + m] = __longlong_as_double((long long)pack2(v, v));
        }
    }

    ull acc01 = 0ull;   // pixels p=0,1 packed
    ull acc23 = 0ull;   // pixels p=2,3 packed

    // ---- two channel chunks of 8 ----
    for (int chunk = 0; chunk < 2; ++chunk) {
        const int ch0 = chunk * CC;

        __syncthreads();   // protect prior-iter tile reads / coeff writes

        // stage x tile (8 channels, 34x34 with zero-padded halo)
        const float* xb = x + ((size_t)(b * C_ + ch0)) * (H_ * W_);
        for (int i = tid; i < CC * PITCH * PITCH; i += NTHREADS) {
            const int c  = i / (PITCH * PITCH);
            const int r  = i - c * (PITCH * PITCH);
            const int yy = r / PITCH;
            const int xx = r - yy * PITCH;
            const int gy = gy0 + yy - 1;
            const int gx = gx0 + xx - 1;
            float v = 0.f;
            if ((unsigned)gy < H_ && (unsigned)gx < W_)
                v = xb[c * (H_ * W_) + gy * W_ + gx];
            sx[i] = v;
        }

        __syncthreads();

        // ---- rational conv accumulate (packed f32x2, 2 pixel-pairs/thread) ----
        #pragma unroll 1
        for (int c = 0; c < CC; ++c) {
            const float*  xc  = sx  + c * (PITCH * PITCH) + ty * PITCH + tx;
            const double* cfb = scf + (ch0 + c) * 90;
            #pragma unroll
            for (int k = 0; k < 9; ++k) {
                const int a  = k / 3;
                const int bb = k - 3 * a;
                const double2* cp = (const double2*)(cfb + k * 10);
                const double2 d0 = cp[0];   // a0 a1
                const double2 d1 = cp[1];   // a2 a3
                const double2 d2 = cp[2];   // a4 a5
                const double2 d3 = cp[3];   // b1 b2
                const double2 d4 = cp[4];   // b3 b4
                const ull A0 = __double_as_longlong(d0.x), A1 = __double_as_longlong(d0.y);
                const ull A2 = __double_as_longlong(d1.x), A3 = __double_as_longlong(d1.y);
                const ull A4 = __double_as_longlong(d2.x), A5 = __double_as_longlong(d2.y);
                const ull B1 = __double_as_longlong(d3.x), B2 = __double_as_longlong(d3.y);
                const ull B3 = __double_as_longlong(d4.x), B4 = __double_as_longlong(d4.y);

                const float xv0 = xc[( 0 + a) * PITCH + bb];
                const float xv1 = xc[( 8 + a) * PITCH + bb];
                const float xv2 = xc[(16 + a) * PITCH + bb];
                const float xv3 = xc[(24 + a) * PITCH + bb];
                const ull xp0 = pack2(xv0, xv1);
                const ull xp1 = pack2(xv2, xv3);

                // ---- pair 0 (pixels 0,1) ----
                {
                    ull P = fma2(A5, xp0, A4);
                    P = fma2(P, xp0, A3);
                    P = fma2(P, xp0, A2);
                    P = fma2(P, xp0, A1);
                    P = fma2(P, xp0, A0);
                    ull S = fma2(B4, xp0, B3);
                    S = fma2(S, xp0, B2);
                    S = fma2(S, xp0, B1);
                    const ull Sx = mul2(S, xp0);
                    float s0, s1;
                    unpack2(Sx, s0, s1);
                    const float r0 = frcp(1.0f + fabsf(s0));
                    const float r1 = frcp(1.0f + fabsf(s1));
                    acc01 = fma2(P, pack2(r0, r1), acc01);
                }
                // ---- pair 1 (pixels 2,3) ----
                {
                    ull P = fma2(A5, xp1, A4);
                    P = fma2(P, xp1, A3);
                    P = fma2(P, xp1, A2);
                    P = fma2(P, xp1, A1);
                    P = fma2(P, xp1, A0);
                    ull S = fma2(B4, xp1, B3);
                    S = fma2(S, xp1, B2);
                    S = fma2(S, xp1, B1);
                    const ull Sx = mul2(S, xp1);
                    float s0, s1;
                    unpack2(Sx, s0, s1);
                    const float r0 = frcp(1.0f + fabsf(s0));
                    const float r1 = frcp(1.0f + fabsf(s1));
                    acc23 = fma2(P, pack2(r0, r1), acc23);
                }
            }
        }
    }

    // ---- write (B,F,H,W): 4 rows per thread, fully coalesced ----
    float a0, a1, a2, a3;
    unpack2(acc01, a0, a1);
    unpack2(acc23, a2, a3);
    float* op = out + ((size_t)blockIdx.z * H_ + gy0 + ty) * W_ + gx0 + tx;
    op[0]                  = a0;
    op[(size_t)( 8) * W_]  = a1;
    op[(size_t)(16) * W_]  = a2;
    op[(size_t)(24) * W_]  = a3;
}

extern "C" void kernel_launch(void* const* d_in, const int* in_sizes, int n_in,
                              void* d_out, int out_size) {
    const float* x      = (const float*)d_in[0];
    const float* nums   = (const float*)d_in[1];
    const float* denoms = (const float*)d_in[2];
    float* out = (float*)d_out;

    dim3 grid(W_ / TW, H_ / TH, B_ * F_);   // 2 x 2 x 128 = 512 blocks, single wave @ occ 4
    dim3 block(32, 8);
    kaconv_kernel<<<grid, block>>>(x, nums, denoms, out);
}

// round 4
// speedup vs baseline: 1.0817x; 1.0152x over previous
#include <cuda_runtime.h>

// Problem constants
#define B_  4
#define C_  16
#define H_  64
#define W_  64
#define F_  32
#define CC  4            // channels per smem chunk (4 chunks)
#define TW  32           // tile width
#define TH  16           // tile height
#define PITCH 34         // tile row pitch (TW + 2 halo)
#define PR  10           // pair-rows per channel (slots r = -1..8 -> 10)
#define SLOT (PR * PITCH)
#define NTHREADS 256

typedef unsigned long long ull;

__device__ __forceinline__ float frcp(float q) {
    float r;
    asm("rcp.approx.f32 %0, %1;" : "=f"(r) : "f"(q));
    return r;
}
__device__ __forceinline__ ull pack2(float lo, float hi) {
    ull r;
    asm("mov.b64 %0, {%1, %2};" : "=l"(r) : "f"(lo), "f"(hi));
    return r;
}
__device__ __forceinline__ void unpack2(ull v, float& lo, float& hi) {
    asm("mov.b64 {%0, %1}, %2;" : "=f"(lo), "=f"(hi) : "l"(v));
}
__device__ __forceinline__ ull fma2(ull a, ull b, ull c) {
    ull d;
    asm("fma.rn.f32x2 %0, %1, %2, %3;" : "=l"(d) : "l"(a), "l"(b), "l"(c));
    return d;
}
__device__ __forceinline__ ull mul2(ull a, ull b) {
    ull d;
    asm("mul.rn.f32x2 %0, %1, %2;" : "=l"(d) : "l"(a), "l"(b));
    return d;
}

__global__ __launch_bounds__(NTHREADS, 7)
void kaconv_kernel(const float* __restrict__ x,
                   const float* __restrict__ nums,
                   const float* __restrict__ denoms,
                   float* __restrict__ out)
{
    // Coeffs duplicated into f32x2 double slots, ordered for Horner consumption:
    // per (c,k): [a5 a4 | a3 a2 | a1 a0 | b4 b3 | b2 b1]   (5 x double2)
    __shared__ __align__(16) double scf[C_ * 9 * 10];   // 11520 B
    // x tile stored as PRE-PACKED pixel pairs: slot(r) holds pack(x[row r-1], x[row r+7])
    __shared__ double spx[CC * SLOT];                   // 10880 B   (total 22400 B)

    const int tx  = threadIdx.x;        // 0..31
    const int ty  = threadIdx.y;        // 0..7
    const int tid = ty * 32 + tx;
    const int f   = blockIdx.z & (F_ - 1);
    const int b   = blockIdx.z >> 5;
    const int gx0 = blockIdx.x * TW;
    const int gy0 = blockIdx.y * TH;

    // ---- stage Pade coefficients for filter f (144 (c,k) slots) ----
    if (tid < C_ * 9) {
        const float* np = nums   + (size_t)f * (C_ * 9 * 6) + tid * 6;
        const float* dp = denoms + (size_t)f * (C_ * 9 * 4) + tid * 4;
        double* dst = scf + tid * 10;
        float a0 = np[0], a1 = np[1], a2 = np[2], a3 = np[3], a4 = np[4], a5 = np[5];
        float b1 = dp[0], b2 = dp[1], b3 = dp[2], b4 = dp[3];
        dst[0] = __longlong_as_double((long long)pack2(a5, a5));
        dst[1] = __longlong_as_double((long long)pack2(a4, a4));
        dst[2] = __longlong_as_double((long long)pack2(a3, a3));
        dst[3] = __longlong_as_double((long long)pack2(a2, a2));
        dst[4] = __longlong_as_double((long long)pack2(a1, a1));
        dst[5] = __longlong_as_double((long long)pack2(a0, a0));
        dst[6] = __longlong_as_double((long long)pack2(b4, b4));
        dst[7] = __longlong_as_double((long long)pack2(b3, b3));
        dst[8] = __longlong_as_double((long long)pack2(b2, b2));
        dst[9] = __longlong_as_double((long long)pack2(b1, b1));
    }

    ull acc = 0ull;   // packed pair: pixel rows (gy0+ty, gy0+ty+8), col gx0+tx

    // ---- four channel chunks of 4 ----
    for (int chunk = 0; chunk < 4; ++chunk) {
        const int ch0 = chunk * CC;

        __syncthreads();   // protect prior-iter tile reads (and coeff writes @chunk 0)

        // stage packed pair tile: slot (c, r, col) = pack(x[gy0+r-1][col], x[gy0+r+7][col])
        const float* xb = x + ((size_t)(b * C_ + ch0)) * (H_ * W_);
        for (int i = tid; i < CC * SLOT; i += NTHREADS) {
            const int c   = i / SLOT;
            const int rem = i - c * SLOT;
            const int r   = rem / PITCH;
            const int col = rem - r * PITCH;
            const int gya = gy0 + r - 1;
            const int gyb = gya + 8;
            const int gx  = gx0 + col - 1;
            const float* xc = xb + c * (H_ * W_);
            float va = 0.f, vb = 0.f;
            if ((unsigned)gx < W_) {
                if ((unsigned)gya < H_) va = xc[gya * W_ + gx];
                if ((unsigned)gyb < H_) vb = xc[gyb * W_ + gx];
            }
            spx[i] = __longlong_as_double((long long)pack2(va, vb));
        }

        __syncthreads();

        // ---- rational conv accumulate (1 packed pair per thread) ----
        #pragma unroll 1
        for (int c = 0; c < CC; ++c) {
            const double*  xp_base = spx + c * SLOT + ty * PITCH + tx;
            const double2* cp = (const double2*)scf + (ch0 + c) * 45;
            #pragma unroll
            for (int k = 0; k < 9; ++k) {
                const int a  = k / 3;
                const int bb = k - 3 * a;
                const double2 d0 = cp[k * 5 + 0];   // a5 a4
                const double2 d1 = cp[k * 5 + 1];   // a3 a2
                const double2 d2 = cp[k * 5 + 2];   // a1 a0
                const double2 d3 = cp[k * 5 + 3];   // b4 b3
                const double2 d4 = cp[k * 5 + 4];   // b2 b1

                const ull xp = __double_as_longlong(xp_base[a * PITCH + bb]);

                ull P = fma2(__double_as_longlong(d0.x), xp, __double_as_longlong(d0.y));
                P = fma2(P, xp, __double_as_longlong(d1.x));
                P = fma2(P, xp, __double_as_longlong(d1.y));
                P = fma2(P, xp, __double_as_longlong(d2.x));
                P = fma2(P, xp, __double_as_longlong(d2.y));

                ull S = fma2(__double_as_longlong(d3.x), xp, __double_as_longlong(d3.y));
                S = fma2(S, xp, __double_as_longlong(d4.x));
                S = fma2(S, xp, __double_as_longlong(d4.y));
                const ull Sx = mul2(S, xp);

                float s0, s1;
                unpack2(Sx, s0, s1);
                const float r0 = frcp(1.0f + fabsf(s0));
                const float r1 = frcp(1.0f + fabsf(s1));
                acc = fma2(P, pack2(r0, r1), acc);
            }
        }
    }

    // ---- write (B,F,H,W): rows ty and ty+8 of this 32x16 tile, coalesced ----
    float a0, a1;
    unpack2(acc, a0, a1);
    float* op = out + ((size_t)blockIdx.z * H_ + gy0 + ty) * W_ + gx0 + tx;
    op[0]                 = a0;
    op[(size_t)8 * W_]    = a1;
}

extern "C" void kernel_launch(void* const* d_in, const int* in_sizes, int n_in,
                              void* d_out, int out_size) {
    const float* x      = (const float*)d_in[0];
    const float* nums   = (const float*)d_in[1];
    const float* denoms = (const float*)d_in[2];
    float* out = (float*)d_out;

    dim3 grid(W_ / TW, H_ / TH, B_ * F_);   // 2 x 4 x 128 = 1024 blocks, single wave @ occ 7
    dim3 block(32, 8);
    kaconv_kernel<<<grid, block>>>(x, nums, denoms, out);
}

// round 5
// speedup vs baseline: 1.1000x; 1.0170x over previous
#include <cuda_runtime.h>

// Problem constants
#define B_  4
#define C_  16
#define H_  64
#define W_  64
#define F_  32
#define CC  4            // channels per smem chunk (4 chunks)
#define TROWS 10         // tile rows incl halo (8 outputs + 2)
#define XPITCH 68        // tile col pitch: logical cols -1..65 at phys 0..66, +1 pad
#define SLOT (TROWS * XPITCH)
#define NTHREADS 128

typedef unsigned long long ull;

__device__ __forceinline__ float frcp(float q) {
    float r;
    asm("rcp.approx.f32 %0, %1;" : "=f"(r) : "f"(q));
    return r;
}
__device__ __forceinline__ ull pack2(float lo, float hi) {
    ull r;
    asm("mov.b64 %0, {%1, %2};" : "=l"(r) : "f"(lo), "f"(hi));
    return r;
}
__device__ __forceinline__ void unpack2(ull v, float& lo, float& hi) {
    asm("mov.b64 {%0, %1}, %2;" : "=f"(lo), "=f"(hi) : "l"(v));
}
__device__ __forceinline__ ull fma2(ull a, ull b, ull c) {
    ull d;
    asm("fma.rn.f32x2 %0, %1, %2, %3;" : "=l"(d) : "l"(a), "l"(b), "l"(c));
    return d;
}
__device__ __forceinline__ ull mul2(ull a, ull b) {
    ull d;
    asm("mul.rn.f32x2 %0, %1, %2;" : "=l"(d) : "l"(a), "l"(b));
    return d;
}

// Evaluate one packed rational tap: acc += P(xp) * rcp(1+|S(xp)*xp|), per lane.
__device__ __forceinline__ void eval_tap(ull xp,
                                         ull A5, ull A4, ull A3, ull A2, ull A1, ull A0,
                                         ull B4, ull B3, ull B2, ull B1,
                                         ull& acc)
{
    ull P = fma2(A5, xp, A4);
    P = fma2(P, xp, A3);
    P = fma2(P, xp, A2);
    P = fma2(P, xp, A1);
    P = fma2(P, xp, A0);
    ull S = fma2(B4, xp, B3);
    S = fma2(S, xp, B2);
    S = fma2(S, xp, B1);
    const ull Sx = mul2(S, xp);
    float s0, s1;
    unpack2(Sx, s0, s1);
    const float r0 = frcp(1.0f + fabsf(s0));
    const float r1 = frcp(1.0f + fabsf(s1));
    acc = fma2(P, pack2(r0, r1), acc);
}

__global__ __launch_bounds__(NTHREADS, 7)
void kaconv_kernel(const float* __restrict__ x,
                   const float* __restrict__ nums,
                   const float* __restrict__ denoms,
                   float* __restrict__ out)
{
    // Coeffs duplicated into f32x2 double slots, Horner order per (c,k):
    // [a5 a4 | a3 a2 | a1 a0 | b4 b3 | b2 b1]  (5 x double2)
    __shared__ __align__(16) double scf[C_ * 9 * 10];   // 11520 B
    // Plain scalar x tile: phys col p = logical col + 1  (logical -1..65)
    __shared__ float sx[CC * SLOT];                      // 10880 B  (total 22400 B)

    const int tx  = threadIdx.x;        // 0..31
    const int ty  = threadIdx.y;        // 0..3
    const int tid = ty * 32 + tx;
    const int f   = blockIdx.z & (F_ - 1);
    const int b   = blockIdx.z >> 5;
    const int gy0 = blockIdx.y * 8;     // 8 output rows per block, full 64-col width

    // ---- stage Pade coefficients for filter f (144 (c,k) slots) ----
    for (int i = tid; i < C_ * 9; i += NTHREADS) {
        const float* np = nums   + (size_t)f * (C_ * 9 * 6) + i * 6;
        const float* dp = denoms + (size_t)f * (C_ * 9 * 4) + i * 4;
        double* dst = scf + i * 10;
        float a0 = np[0], a1 = np[1], a2 = np[2], a3 = np[3], a4 = np[4], a5 = np[5];
        float b1 = dp[0], b2 = dp[1], b3 = dp[2], b4 = dp[3];
        dst[0] = __longlong_as_double((long long)pack2(a5, a5));
        dst[1] = __longlong_as_double((long long)pack2(a4, a4));
        dst[2] = __longlong_as_double((long long)pack2(a3, a3));
        dst[3] = __longlong_as_double((long long)pack2(a2, a2));
        dst[4] = __longlong_as_double((long long)pack2(a1, a1));
        dst[5] = __longlong_as_double((long long)pack2(a0, a0));
        dst[6] = __longlong_as_double((long long)pack2(b4, b4));
        dst[7] = __longlong_as_double((long long)pack2(b3, b3));
        dst[8] = __longlong_as_double((long long)pack2(b2, b2));
        dst[9] = __longlong_as_double((long long)pack2(b1, b1));
    }

    // Each thread: output cols (2tx, 2tx+1), rows gy0+ty and gy0+ty+4.
    ull acc0 = 0ull;   // row ty:   packed (col 2tx, col 2tx+1)
    ull acc1 = 0ull;   // row ty+4

    // ---- four channel chunks of 4 ----
    for (int chunk = 0; chunk < 4; ++chunk) {
        const int ch0 = chunk * CC;

        __syncthreads();   // protect prior-iter tile reads (and coeff writes @chunk 0)

        // stage x tile: rows gy0-1..gy0+8, logical cols -1..65 (phys 0..66)
        const float* xb = x + ((size_t)(b * C_ + ch0)) * (H_ * W_);
        for (int i = tid; i < CC * SLOT; i += NTHREADS) {
            const int c   = i / SLOT;
            const int rem = i - c * SLOT;
            const int r   = rem / XPITCH;
            const int p   = rem - r * XPITCH;
            const int gy  = gy0 + r - 1;
            const int gx  = p - 1;            // logical col
            float v = 0.f;
            if ((unsigned)gy < H_ && (unsigned)gx < W_)
                v = xb[c * (H_ * W_) + gy * W_ + gx];
            sx[i] = v;
        }

        __syncthreads();

        // ---- rational conv accumulate ----
        #pragma unroll 1
        for (int c = 0; c < CC; ++c) {
            // thread base: row index in tile for a=0 is ty (tile row = gy - gy0 + 1),
            // phys col of logical (2tx-1) is 2tx.
            const float*  xc = sx + c * SLOT + ty * XPITCH + 2 * tx;
            const double2* cp = (const double2*)(scf + (ch0 + c) * 90);
            #pragma unroll
            for (int a = 0; a < 3; ++a) {
                // row for acc0 taps: tile row ty+a ; for acc1: ty+a+4
                const ull u00 = *(const ull*)(xc + a * XPITCH);           // cols 2tx-1,2tx
                const ull u01 = *(const ull*)(xc + a * XPITCH + 2);       // cols 2tx+1,2tx+2
                const ull u10 = *(const ull*)(xc + (a + 4) * XPITCH);
                const ull u11 = *(const ull*)(xc + (a + 4) * XPITCH + 2);
                float w0, x0, y0, z0, w1, x1, y1, z1;
                unpack2(u00, w0, x0); unpack2(u01, y0, z0);
                unpack2(u10, w1, x1); unpack2(u11, y1, z1);
                const ull xp0[3] = { u00, pack2(x0, y0), u01 };
                const ull xp1[3] = { u10, pack2(x1, y1), u11 };
                #pragma unroll
                for (int bb = 0; bb < 3; ++bb) {
                    const double2 d0 = cp[(a * 3 + bb) * 5 + 0];   // a5 a4
                    const double2 d1 = cp[(a * 3 + bb) * 5 + 1];   // a3 a2
                    const double2 d2 = cp[(a * 3 + bb) * 5 + 2];   // a1 a0
                    const double2 d3 = cp[(a * 3 + bb) * 5 + 3];   // b4 b3
                    const double2 d4 = cp[(a * 3 + bb) * 5 + 4];   // b2 b1
                    const ull A5 = __double_as_longlong(d0.x), A4 = __double_as_longlong(d0.y);
                    const ull A3 = __double_as_longlong(d1.x), A2 = __double_as_longlong(d1.y);
                    const ull A1 = __double_as_longlong(d2.x), A0 = __double_as_longlong(d2.y);
                    const ull B4 = __double_as_longlong(d3.x), B3 = __double_as_longlong(d3.y);
                    const ull B2 = __double_as_longlong(d4.x), B1 = __double_as_longlong(d4.y);
                    eval_tap(xp0[bb], A5, A4, A3, A2, A1, A0, B4, B3, B2, B1, acc0);
                    eval_tap(xp1[bb], A5, A4, A3, A2, A1, A0, B4, B3, B2, B1, acc1);
                }
            }
        }
    }

    // ---- write (B,F,H,W): two adjacent floats per row -> STG.64, coalesced ----
    float o00, o01, o10, o11;
    unpack2(acc0, o00, o01);
    unpack2(acc1, o10, o11);
    float* op = out + ((size_t)blockIdx.z * H_ + gy0 + ty) * W_ + 2 * tx;
    ((float2*)op)[0]                      = make_float2(o00, o01);
    ((float2*)(op + (size_t)4 * W_))[0]   = make_float2(o10, o11);
}

extern "C" void kernel_launch(void* const* d_in, const int* in_sizes, int n_in,
                              void* d_out, int out_size) {
    const float* x      = (const float*)d_in[0];
    const float* nums   = (const float*)d_in[1];
    const float* denoms = (const float*)d_in[2];
    float* out = (float*)d_out;

    dim3 grid(1, H_ / 8, B_ * F_);   // 1 x 8 x 128 = 1024 blocks, single wave @ occ 7
    dim3 block(32, 4);
    kaconv_kernel<<<grid, block>>>(x, nums, denoms, out);
}